// round 2
// baseline (speedup 1.0000x reference)
#include <cuda_runtime.h>
#include <cstdint>

// Problem shape (fixed for this dataset entry)
#define BATCH 64
#define TT    2048
#define DD    256
#define HH    256

// ---------------------------------------------------------------------------
// Kernel A: xp = x @ Wxh + bias     (M = B*T rows, K = D, N = H)
// Classic fp32 register-tiled SGEMM. BM=128, BN=128, BK=8, 256 threads,
// 8x8 micro-tile per thread. Writes result into d_out (used as xp scratch).
// ---------------------------------------------------------------------------
#define BM 128
#define BN 128
#define BK 8
#define TM 8
#define TN 8

__global__ __launch_bounds__(256) void xp_gemm_kernel(
    const float* __restrict__ X,     // [M, D]
    const float* __restrict__ W,     // [D, H] row-major
    const float* __restrict__ bias,  // [H]
    float* __restrict__ out)         // [M, H]
{
    __shared__ float As[BK][BM];
    __shared__ float Bs[BK][BN];

    const int m0 = blockIdx.x * BM;
    const int n0 = blockIdx.y * BN;
    const int tid = threadIdx.x;
    const int tx = tid & 15;   // N direction (16)
    const int ty = tid >> 4;   // M direction (16)

    // A-tile load mapping: 128 rows x 8 k -> 1024 floats, one float4/thread
    const int a_r = tid >> 1;          // 0..127
    const int a_k = (tid & 1) * 4;     // 0 or 4
    // B-tile load mapping: 8 rows x 128 n -> 1024 floats, one float4/thread
    const int b_r = tid >> 5;          // 0..7
    const int b_n = (tid & 31) * 4;    // 0..124

    float acc[TM][TN];
#pragma unroll
    for (int i = 0; i < TM; i++)
#pragma unroll
        for (int j = 0; j < TN; j++) acc[i][j] = 0.f;

    const float* Xp = X + (long long)m0 * DD;

    for (int k0 = 0; k0 < DD; k0 += BK) {
        float4 av = *reinterpret_cast<const float4*>(Xp + (long long)a_r * DD + k0 + a_k);
        As[a_k + 0][a_r] = av.x;
        As[a_k + 1][a_r] = av.y;
        As[a_k + 2][a_r] = av.z;
        As[a_k + 3][a_r] = av.w;
        float4 bv = *reinterpret_cast<const float4*>(W + (long long)(k0 + b_r) * HH + n0 + b_n);
        *reinterpret_cast<float4*>(&Bs[b_r][b_n]) = bv;
        __syncthreads();

#pragma unroll
        for (int k = 0; k < BK; k++) {
            float ar[TM], br[TN];
#pragma unroll
            for (int i = 0; i < TM; i++) ar[i] = As[k][ty * TM + i];
#pragma unroll
            for (int j = 0; j < TN; j++) br[j] = Bs[k][tx * TN + j];
#pragma unroll
            for (int i = 0; i < TM; i++)
#pragma unroll
                for (int j = 0; j < TN; j++) acc[i][j] += ar[i] * br[j];
        }
        __syncthreads();
    }

    // Epilogue: add bias, store as float4
    float bv[TN];
#pragma unroll
    for (int j = 0; j < TN; j++) bv[j] = bias[n0 + tx * TN + j];

#pragma unroll
    for (int i = 0; i < TM; i++) {
        const int row = m0 + ty * TM + i;
        float* op = out + (long long)row * HH + n0 + tx * TN;
        float4 r0, r1;
        r0.x = acc[i][0] + bv[0]; r0.y = acc[i][1] + bv[1];
        r0.z = acc[i][2] + bv[2]; r0.w = acc[i][3] + bv[3];
        r1.x = acc[i][4] + bv[4]; r1.y = acc[i][5] + bv[5];
        r1.z = acc[i][6] + bv[6]; r1.w = acc[i][7] + bv[7];
        *reinterpret_cast<float4*>(op)     = r0;
        *reinterpret_cast<float4*>(op + 4) = r1;
    }
}

// ---------------------------------------------------------------------------
// Kernel B: persistent recurrence. One CTA per batch element.
// 256 threads; thread == output column. Per column:
//   Whh rows [0,192) kept in registers (192 floats / thread),
//   Whh rows [192,256) in smem packed float4 [k4][col] (64 KB).
// h lives in smem (256 floats). xp read from d_out[b,t,:] (written by kernel A)
// and overwritten in-place with h_t. xp for t+1 prefetched during step t.
// ---------------------------------------------------------------------------
#define WREG 192
#define WSMEM_ROWS 64
#define WSMEM_K4 (WSMEM_ROWS / 4)     // 16
// smem: 16*256 float4 (65536B) + 256 floats h (1024B)
#define RNN_SMEM_BYTES (WSMEM_K4 * HH * 16 + HH * 4)

__global__ __launch_bounds__(256, 1) void rnn_rec_kernel(
    const float* __restrict__ Whh,   // [H, H] row-major
    float* __restrict__ out)         // [B, T, H]  (holds xp on entry)
{
    extern __shared__ float4 smem4[];
    float4* Whs4 = smem4;                                   // [16][256]
    float* hs = reinterpret_cast<float*>(smem4 + WSMEM_K4 * HH);  // [256]
    const float4* hs4 = reinterpret_cast<const float4*>(hs);

    const int col = threadIdx.x;
    const int b = blockIdx.x;

    // --- one-time: load Whh column slices ---
    float w[WREG];
#pragma unroll
    for (int k = 0; k < WREG; k++) w[k] = Whh[k * HH + col];

#pragma unroll
    for (int k4 = 0; k4 < WSMEM_K4; k4++) {
        float4 wv;
        wv.x = Whh[(WREG + 4 * k4 + 0) * HH + col];
        wv.y = Whh[(WREG + 4 * k4 + 1) * HH + col];
        wv.z = Whh[(WREG + 4 * k4 + 2) * HH + col];
        wv.w = Whh[(WREG + 4 * k4 + 3) * HH + col];
        Whs4[k4 * HH + col] = wv;
    }

    hs[col] = 0.f;
    __syncthreads();

    float* orow = out + (long long)b * TT * HH;
    float xpv = orow[col];  // xp at t=0

#pragma unroll 1
    for (int t = 0; t < TT; t++) {
        // Prefetch next step's xp (off critical path)
        float xnext = 0.f;
        if (t + 1 < TT) xnext = orow[(t + 1) * HH + col];

        float acc0 = 0.f, acc1 = 0.f, acc2 = 0.f, acc3 = 0.f;

        // Register-resident part of Whh: k in [0, 192)
#pragma unroll
        for (int k4 = 0; k4 < WREG / 4; k4++) {
            float4 hv = hs4[k4];
            acc0 += hv.x * w[4 * k4 + 0];
            acc1 += hv.y * w[4 * k4 + 1];
            acc2 += hv.z * w[4 * k4 + 2];
            acc3 += hv.w * w[4 * k4 + 3];
        }
        // Smem-resident part: k in [192, 256)
#pragma unroll
        for (int k4 = 0; k4 < WSMEM_K4; k4++) {
            float4 hv = hs4[WREG / 4 + k4];
            float4 wv = Whs4[k4 * HH + col];
            acc0 += hv.x * wv.x;
            acc1 += hv.y * wv.y;
            acc2 += hv.z * wv.z;
            acc3 += hv.w * wv.w;
        }

        float v = tanhf(xpv + ((acc0 + acc1) + (acc2 + acc3)));

        __syncthreads();              // everyone done reading old h
        hs[col] = v;
        orow[t * HH + col] = v;       // overwrite xp slot with h_t
        xpv = xnext;
        __syncthreads();              // new h visible
    }
}

// ---------------------------------------------------------------------------
extern "C" void kernel_launch(void* const* d_in, const int* in_sizes, int n_in,
                              void* d_out, int out_size)
{
    const float* x    = (const float*)d_in[0];   // [B, T, D]
    const float* Wxh  = (const float*)d_in[1];   // [D, H]
    const float* Whh  = (const float*)d_in[2];   // [H, H]
    const float* bias = (const float*)d_in[3];   // [H]
    float* out = (float*)d_out;                  // [B, T, H]

    const int M = in_sizes[0] / DD;              // B*T = 131072

    // Phase 1: xp = x @ Wxh + b  -> out (scratch)
    dim3 gridA(M / BM, HH / BN);
    xp_gemm_kernel<<<gridA, 256>>>(x, Wxh, bias, out);

    // Phase 2: recurrence in-place on out
    cudaFuncSetAttribute(rnn_rec_kernel,
                         cudaFuncAttributeMaxDynamicSharedMemorySize,
                         RNN_SMEM_BYTES);
    rnn_rec_kernel<<<BATCH, 256, RNN_SMEM_BYTES>>>(Whh, out);
}

// round 3
// speedup vs baseline: 1.2026x; 1.2026x over previous
#include <cuda_runtime.h>
#include <cstdint>

// Problem shape (fixed)
#define BATCH 64
#define TT    2048
#define DD    256
#define HH    256

// Packed fp32x2 FMA (sm_100+ PTX; ptxas never emits this from C++)
#define FMA2(acc, a, b) \
    asm("fma.rn.f32x2 %0, %1, %2, %0;" : "+l"(acc) : "l"(a), "l"(b))
#define SPLAT2(dst, s) \
    asm("mov.b64 %0, {%1, %1};" : "=l"(dst) : "f"(s))
#define PACK2(dst, lo, hi) \
    asm("mov.b64 %0, {%1, %2};" : "=l"(dst) : "f"(lo), "f"(hi))
#define UNPACK2(lo, hi, src) \
    asm("mov.b64 {%0, %1}, %2;" : "=f"(lo), "=f"(hi) : "l"(src))

// ---------------------------------------------------------------------------
// Kernel A: xp = x @ Wxh + bias   (M=B*T, K=D, N=H), f32x2 inner product
// BM=128, BN=128, BK=8, 256 threads, 8x8 micro-tile (as 8x4 f32x2 pairs)
// ---------------------------------------------------------------------------
#define BM 128
#define BN 128
#define BK 8
#define TM 8
#define TN 8

__global__ __launch_bounds__(256) void xp_gemm_kernel(
    const float* __restrict__ X,
    const float* __restrict__ W,
    const float* __restrict__ bias,
    float* __restrict__ out)
{
    __shared__ float As[BK][BM];
    __shared__ __align__(16) float Bs[BK][BN];

    const int m0 = blockIdx.x * BM;
    const int n0 = blockIdx.y * BN;
    const int tid = threadIdx.x;
    const int tx = tid & 15;   // N
    const int ty = tid >> 4;   // M

    const int a_r = tid >> 1;
    const int a_k = (tid & 1) * 4;
    const int b_r = tid >> 5;
    const int b_n = (tid & 31) * 4;

    // accumulators: 8 rows x 4 f32x2 pairs (cols tx*8 + {0,1},{2,3},{4,5},{6,7})
    unsigned long long acc[TM][TN / 2];
#pragma unroll
    for (int i = 0; i < TM; i++)
#pragma unroll
        for (int j = 0; j < TN / 2; j++) acc[i][j] = 0ull;

    const float* Xp = X + (long long)m0 * DD;

    for (int k0 = 0; k0 < DD; k0 += BK) {
        float4 av = *reinterpret_cast<const float4*>(Xp + (long long)a_r * DD + k0 + a_k);
        As[a_k + 0][a_r] = av.x;
        As[a_k + 1][a_r] = av.y;
        As[a_k + 2][a_r] = av.z;
        As[a_k + 3][a_r] = av.w;
        float4 bv = *reinterpret_cast<const float4*>(W + (long long)(k0 + b_r) * HH + n0 + b_n);
        *reinterpret_cast<float4*>(&Bs[b_r][b_n]) = bv;
        __syncthreads();

#pragma unroll
        for (int k = 0; k < BK; k++) {
            // B pairs: 4 x f32x2 via two 16B loads
            ulonglong2 b01 = *reinterpret_cast<const ulonglong2*>(&Bs[k][tx * TN]);
            ulonglong2 b23 = *reinterpret_cast<const ulonglong2*>(&Bs[k][tx * TN + 4]);
            float ar[TM];
#pragma unroll
            for (int i = 0; i < TM; i++) ar[i] = As[k][ty * TM + i];
#pragma unroll
            for (int i = 0; i < TM; i++) {
                unsigned long long ai;
                SPLAT2(ai, ar[i]);
                FMA2(acc[i][0], ai, b01.x);
                FMA2(acc[i][1], ai, b01.y);
                FMA2(acc[i][2], ai, b23.x);
                FMA2(acc[i][3], ai, b23.y);
            }
        }
        __syncthreads();
    }

    float bv[TN];
#pragma unroll
    for (int j = 0; j < TN; j++) bv[j] = bias[n0 + tx * TN + j];

#pragma unroll
    for (int i = 0; i < TM; i++) {
        const int row = m0 + ty * TM + i;
        float* op = out + (long long)row * HH + n0 + tx * TN;
        float r[TN];
#pragma unroll
        for (int j = 0; j < TN / 2; j++) {
            UNPACK2(r[2 * j], r[2 * j + 1], acc[i][j]);
        }
        float4 r0, r1;
        r0.x = r[0] + bv[0]; r0.y = r[1] + bv[1];
        r0.z = r[2] + bv[2]; r0.w = r[3] + bv[3];
        r1.x = r[4] + bv[4]; r1.y = r[5] + bv[5];
        r1.z = r[6] + bv[6]; r1.w = r[7] + bv[7];
        *reinterpret_cast<float4*>(op)     = r0;
        *reinterpret_cast<float4*>(op + 4) = r1;
    }
}

// ---------------------------------------------------------------------------
// Kernel B: recurrence. One CTA per batch, 256 threads, thread == column.
// Whh split: rows [0,216) in registers as 108 f32x2 pairs; rows [216,256)
// in smem as ulonglong2 [10][256] (40KB). h double-buffered in smem
// (one barrier per step). All FMAs are packed f32x2.
// ---------------------------------------------------------------------------
#define WPAIRS 108              // f32x2 pairs in registers (216 rows)
#define WROWS_SM 40             // rows in smem
#define WGROUPS (WROWS_SM / 4)  // 10 ulonglong2 per column

__global__ __launch_bounds__(256, 1) void rnn_rec_kernel(
    const float* __restrict__ Whh,
    float* __restrict__ out)
{
    __shared__ ulonglong2 Wsh[WGROUPS * HH];               // 40KB
    __shared__ __align__(16) float hbuf[2][HH];            // 2KB

    const int col = threadIdx.x;
    const int b = blockIdx.x;

    // one-time: register pairs for rows [0, 216)
    unsigned long long wp[WPAIRS];
#pragma unroll
    for (int p = 0; p < WPAIRS; p++) {
        float w0 = Whh[(2 * p + 0) * HH + col];
        float w1 = Whh[(2 * p + 1) * HH + col];
        PACK2(wp[p], w0, w1);
    }
    // one-time: smem pairs for rows [216, 256)
#pragma unroll
    for (int g = 0; g < WGROUPS; g++) {
        const int r = 2 * WPAIRS + 4 * g;
        float w0 = Whh[(r + 0) * HH + col];
        float w1 = Whh[(r + 1) * HH + col];
        float w2 = Whh[(r + 2) * HH + col];
        float w3 = Whh[(r + 3) * HH + col];
        ulonglong2 wv;
        PACK2(wv.x, w0, w1);
        PACK2(wv.y, w2, w3);
        Wsh[g * HH + col] = wv;
    }

    hbuf[0][col] = 0.f;
    __syncthreads();

    float* orow = out + (long long)b * TT * HH;
    float xpv = orow[col];

    const float* cur = hbuf[0];
    float* nxt = hbuf[1];

#pragma unroll 1
    for (int t = 0; t < TT; t++) {
        float xnext = 0.f;
        if (t + 1 < TT) xnext = orow[(t + 1) * HH + col];

        const ulonglong2* h2 = reinterpret_cast<const ulonglong2*>(cur);

        unsigned long long a0 = 0ull, a1 = 0ull, a2 = 0ull, a3 = 0ull;

        // register-Whh part: rows [0, 216), 54 ulonglong2 of h
#pragma unroll
        for (int j = 0; j < WPAIRS / 4; j++) {      // 27 iters, 2 h2 loads each
            ulonglong2 hA = h2[2 * j];
            ulonglong2 hB = h2[2 * j + 1];
            FMA2(a0, hA.x, wp[4 * j + 0]);
            FMA2(a1, hA.y, wp[4 * j + 1]);
            FMA2(a2, hB.x, wp[4 * j + 2]);
            FMA2(a3, hB.y, wp[4 * j + 3]);
        }
        // smem-Whh part: rows [216, 256)
#pragma unroll
        for (int g = 0; g < WGROUPS; g++) {
            ulonglong2 wv = Wsh[g * HH + col];
            ulonglong2 hv = h2[WPAIRS / 2 + g];
            FMA2(a0, hv.x, wv.x);
            FMA2(a1, hv.y, wv.y);
        }

        float s0, s1, s2, s3, s4, s5, s6, s7;
        UNPACK2(s0, s1, a0);
        UNPACK2(s2, s3, a1);
        UNPACK2(s4, s5, a2);
        UNPACK2(s6, s7, a3);
        float v = tanhf(xpv + (((s0 + s1) + (s2 + s3)) + ((s4 + s5) + (s6 + s7))));

        nxt[col] = v;
        orow[t * HH + col] = v;
        __syncthreads();             // single barrier: double-buffered h

        const float* tmp = cur; cur = nxt; nxt = const_cast<float*>(tmp);
        xpv = xnext;
    }
}

// ---------------------------------------------------------------------------
extern "C" void kernel_launch(void* const* d_in, const int* in_sizes, int n_in,
                              void* d_out, int out_size)
{
    const float* x    = (const float*)d_in[0];
    const float* Wxh  = (const float*)d_in[1];
    const float* Whh  = (const float*)d_in[2];
    const float* bias = (const float*)d_in[3];
    float* out = (float*)d_out;

    const int M = in_sizes[0] / DD;   // B*T

    dim3 gridA(M / BM, HH / BN);
    xp_gemm_kernel<<<gridA, 256>>>(x, Wxh, bias, out);

    rnn_rec_kernel<<<BATCH, 256>>>(Whh, out);
}